// round 15
// baseline (speedup 1.0000x reference)
#include <cuda_runtime.h>
#include <cstdint>

#define B_ 8
#define N_ 1024
#define I_ 64
#define O_ 32
#define NW 32
#define H_ 4
#define PS4 10             // k2 P-tile row stride in float4 (phase-conflict-free)
#define XS 68              // k01 x smem stride (floats)
#define WS 136             // k01 W smem stride (floats)
#define LOG2E 1.4426950408889634f

// ---- device scratch ----
__device__ float    g_proj[B_*H_*N_*O_];    // [bh][j][operm], tf32-rounded
__device__ float2   g_srcsp[B_*H_*N_];      // (src*L, gain*prior*L)
__device__ float    g_dstsc[B_*H_*N_];      // dst*L
__device__ unsigned g_adjp[(N_/2)*NW*2];    // row-pair interleaved adjacency bits

__device__ __forceinline__ float tf32r(float x) {
    uint32_t r;
    asm("cvt.rna.tf32.f32 %0, %1;" : "=r"(r) : "f"(x));
    return __uint_as_float(r);
}
__device__ __forceinline__ uint32_t tf32u(float x) {
    uint32_t r;
    asm("cvt.rna.tf32.f32 %0, %1;" : "=r"(r) : "f"(x));
    return r;
}
__device__ __forceinline__ float ex2f(float x) {
    float r;
    asm("ex2.approx.f32 %0, %1;" : "=f"(r) : "f"(x));
    return r;
}
__device__ __forceinline__ unsigned long long pk2(float a, float b) {
    unsigned long long r;
    asm("mov.b64 %0, {%1, %2};" : "=l"(r) : "f"(a), "f"(b));
    return r;
}
__device__ __forceinline__ unsigned long long add2(unsigned long long a, unsigned long long b) {
    unsigned long long r;
    asm("add.rn.f32x2 %0, %1, %2;" : "=l"(r) : "l"(a), "l"(b));
    return r;
}
__device__ __forceinline__ unsigned long long fma2p(unsigned long long a, unsigned long long b,
                                                    unsigned long long c) {
    unsigned long long r;
    asm("fma.rn.f32x2 %0, %1, %2, %3;" : "=l"(r) : "l"(a), "l"(b), "l"(c));
    return r;
}
__device__ __forceinline__ void upk2(unsigned long long v, float& a, float& b) {
    asm("mov.b64 {%0, %1}, %2;" : "=f"(a), "=f"(b) : "l"(v));
}
__device__ __forceinline__ void mma8(float* c, uint32_t a0, uint32_t a1, uint32_t a2,
                                     uint32_t a3, uint32_t b0, uint32_t b1) {
    asm volatile(
        "mma.sync.aligned.m16n8k8.row.col.f32.tf32.tf32.f32 "
        "{%0,%1,%2,%3}, {%4,%5,%6,%7}, {%8,%9}, {%0,%1,%2,%3};"
        : "+f"(c[0]), "+f"(c[1]), "+f"(c[2]), "+f"(c[3])
        : "r"(a0), "r"(a1), "r"(a2), "r"(a3), "r"(b0), "r"(b1));
}

// =============== K01: pack (blocks 0..127) + tf32 MMA proj/scores (128..383) ===============
__global__ __launch_bounds__(256) void k01_prep(
    const int* __restrict__ adj,
    const float* __restrict__ x, const float* __restrict__ weight,
    const float* __restrict__ bias, const float* __restrict__ attn_src,
    const float* __restrict__ attn_dst, const float* __restrict__ beta,
    const float* __restrict__ prior)
{
    __shared__ float s_x[32*XS];           // 8.7KB
    __shared__ float s_w[I_*WS];           // 34.8KB  W as [i][ho]; reused as s_out
    __shared__ float s_ws[H_*I_];
    __shared__ float s_wd[H_*I_];
    __shared__ float s_c[8];
    int tid = threadIdx.x, lane = tid & 31, w = tid >> 5;
    int g = lane >> 2, q4 = lane & 3;

    if (blockIdx.x < 128) {
        // ---- pack: one warp per adjacency row, 8 front-batched int4 loads ----
        int i = blockIdx.x * 8 + w;
        const int4* a4 = (const int4*)(adj + (size_t)i * N_);
        int4 v[8];
#pragma unroll
        for (int c4 = 0; c4 < 8; c4++) v[c4] = a4[c4 * 32 + lane];

        int gs = lane >> 3;
        unsigned gmask = 0xFFu << (gs * 8);
        int sh = (lane & 7) * 4;
        int pidx = (i >> 4) * 8 + (i & 7);
        int comp = (i >> 3) & 1;
#pragma unroll
        for (int c4 = 0; c4 < 8; c4++) {
            unsigned nib = (unsigned)(v[c4].x != 0) | ((unsigned)(v[c4].y != 0) << 1)
                         | ((unsigned)(v[c4].z != 0) << 2) | ((unsigned)(v[c4].w != 0) << 3);
            unsigned word = __reduce_or_sync(gmask, nib << sh);
            if ((lane & 7) == 0) g_adjp[(pidx * NW + c4 * 4 + gs) * 2 + comp] = word;
        }
        return;
    }

    int pb = blockIdx.x - 128;             // [0,256)
    int g0 = pb * 32;
    int b  = g0 >> 10;

    // stage x [32 x 64], padded
    {
        const float4* gx4 = (const float4*)(x + (size_t)g0 * I_);
#pragma unroll
        for (int u = 0; u < 2; u++) {
            int idx = tid + u * 256;
            int node = idx >> 4, i4 = idx & 15;
            *(float4*)(s_x + node * XS + i4 * 4) = gx4[idx];
        }
    }
    // stage W as [i][ho], padded
    {
        const float4* gw4 = (const float4*)weight;
#pragma unroll
        for (int u = 0; u < 8; u++) {
            int l4 = tid + u * 256;
            int h = l4 >> 9, i = (l4 >> 3) & 63, o4 = l4 & 7;
            *(float4*)(s_w + i * WS + h * O_ + o4 * 4) = gw4[l4];
        }
    }
    // score contraction vectors
    {
        int h = tid >> 6;
        const float4* wrow = (const float4*)(weight + (size_t)tid * O_);
        const float4* as4  = (const float4*)(attn_src + h * O_);
        const float4* ad4  = (const float4*)(attn_dst + h * O_);
        float accs = 0.f, accd = 0.f;
#pragma unroll
        for (int o4 = 0; o4 < 8; o4++) {
            float4 wv = wrow[o4], av = as4[o4], dv = ad4[o4];
            accs += wv.x*av.x + wv.y*av.y + wv.z*av.z + wv.w*av.w;
            accd += wv.x*dv.x + wv.y*dv.y + wv.z*dv.z + wv.w*dv.w;
        }
        s_ws[tid] = accs * LOG2E;
        s_wd[tid] = accd * LOG2E;
    }
    if (tid < 8) {
        int hh = tid & 3;
        const float* bb = bias + hh * O_;
        const float* aa = (tid < 4 ? attn_src : attn_dst) + hh * O_;
        float c = 0.f;
#pragma unroll
        for (int o = 0; o < O_; o++) c += bb[o] * aa[o];
        s_c[tid] = c * LOG2E;
    }
    __syncthreads();

    // ---- projection: single-pass tf32 MMA, bias in accumulator init ----
    float acc[4][4];
    {
        int wn = w >> 1, mt = w & 1;
#pragma unroll
        for (int nt = 0; nt < 4; nt++) {
            float b0 = bias[wn * 32 + nt * 8 + 2 * q4];
            float b1 = bias[wn * 32 + nt * 8 + 2 * q4 + 1];
            acc[nt][0] = b0; acc[nt][1] = b1; acc[nt][2] = b0; acc[nt][3] = b1;
        }
#pragma unroll
        for (int ks = 0; ks < 8; ks++) {
            int i0 = ks * 8;
            uint32_t a0 = tf32u(s_x[(mt*16 + g    ) * XS + i0 + q4]);
            uint32_t a1 = tf32u(s_x[(mt*16 + g + 8) * XS + i0 + q4]);
            uint32_t a2 = tf32u(s_x[(mt*16 + g    ) * XS + i0 + q4 + 4]);
            uint32_t a3 = tf32u(s_x[(mt*16 + g + 8) * XS + i0 + q4 + 4]);
#pragma unroll
            for (int nt = 0; nt < 4; nt++) {
                int col = wn * 32 + nt * 8 + g;
                uint32_t b0 = tf32u(s_w[(i0 + q4    ) * WS + col]);
                uint32_t b1 = tf32u(s_w[(i0 + q4 + 4) * WS + col]);
                mma8(acc[nt], a0, a1, a2, a3, b0, b1);
            }
        }
    }
    __syncthreads();                       // all s_w reads complete

    // ---- epilogue: stage to smem (reuse s_w), then coalesced STG.128 ----
    {
        int wn = w >> 1, mt = w & 1;
        float* s_out = s_w;                // [node 0..31][128: h*32+operm]
#pragma unroll
        for (int nt = 0; nt < 4; nt++) {
#pragma unroll
            for (int c2 = 0; c2 < 2; c2++) {
                int ho = wn * 32 + nt * 8 + 2 * q4 + c2;
                int h = ho >> 5, o = ho & 31;
                int col = h * 32 + (o & 7) * 4 + (o >> 3);
                s_out[(mt*16 + g    ) * 128 + col] = tf32r(acc[nt][c2]);
                s_out[(mt*16 + g + 8) * 128 + col] = tf32r(acc[nt][c2 + 2]);
            }
        }
    }
    __syncthreads();

    {
        int n0 = g0 & 1023;
        const float4* so4 = (const float4*)s_w;
#pragma unroll
        for (int u = 0; u < 4; u++) {
            int idx = tid + u * 256;       // 1024 float4
            int n = idx >> 5, c4 = idx & 31;
            int h = c4 >> 3, o4 = c4 & 7;
            ((float4*)g_proj)[((size_t)(b * H_ + h) * N_ + n0 + n) * 8 + o4] = so4[idx];
        }
    }

    // ---- scores (exact fp32) ----
    {
        int role = tid >> 7, local = tid & 127;
        int n = local >> 2, hs = local & 3;
        const float4* xv4 = (const float4*)(s_x + n * XS);
        const float4* wv4 = (const float4*)((role ? s_wd : s_ws) + hs * I_);
        float sc = s_c[role * 4 + hs];
#pragma unroll
        for (int i4 = 0; i4 < I_/4; i4++) {
            float4 xv = xv4[i4], wv = wv4[i4];
            sc += xv.x*wv.x + xv.y*wv.y + xv.z*wv.z + xv.w*wv.w;
        }
        int gidx = g0 + n;
        int idx = (b * H_ + hs) * N_ + (gidx & 1023);
        if (role) {
            g_dstsc[idx] = sc;
        } else {
            float bt = beta[hs];
            float gain = ((bt > 20.f) ? bt : log1pf(__expf(bt))) * LOG2E;
            g_srcsp[idx] = make_float2(sc, gain * prior[gidx]);
        }
    }
}

// =============== K2: 4-way j-split, packed-f32x2 logits, dn-in-MMA ===============
__global__ __launch_bounds__(512, 2) void k2_attn(float* __restrict__ out) {
    __shared__ ulonglong2 s_ssd[N_];       // 16KB: per j (x,x | y,y) packed pairs
    __shared__ float      s_P[4][64*PS4*4];// 41KB

    int tid = threadIdx.x, lane = tid & 31, w = tid >> 5;
    int h = blockIdx.y, b = blockIdx.z, bh = b * H_ + h;
    int row0 = blockIdx.x * 64;

    const float2* gss = g_srcsp + (size_t)bh * N_;
#pragma unroll
    for (int u = 0; u < 2; u++) {
        int j = tid + u * 512;
        float2 ss = gss[j];
        s_ssd[j] = make_ulonglong2(pk2(ss.x, ss.x), pk2(ss.y, ss.y));
    }
    __syncthreads();

    int grp = w >> 2;
    int wl4 = w & 3;
    int g   = lane >> 2;
    int q4  = lane & 3;
    int lt  = tid & 127;
    int barid = grp + 1;

    int r_lo = wl4 * 16 + g, r_hi = r_lo + 8;
    unsigned long long dd = pk2(g_dstsc[(size_t)bh * N_ + row0 + r_lo],
                                g_dstsc[(size_t)bh * N_ + row0 + r_hi]);
    const unsigned long long C06 = 0x3F19999A3F19999Aull;   // (0.6f, 0.6f)
    const unsigned long long C04 = 0x3ECCCCCD3ECCCCCDull;   // (0.4f, 0.4f)
    const unsigned long long ABS2 = 0x7FFFFFFF7FFFFFFFull;
    int pidx = ((row0 + wl4 * 16) >> 4) * 8 + g;
    const uint2* ap = (const uint2*)g_adjp + (size_t)pidx * NW;

    float acc[4][4], accd[4];
#pragma unroll
    for (int nc = 0; nc < 4; nc++) {
        accd[nc] = 0.f;
#pragma unroll
        for (int k = 0; k < 4; k++) acc[nc][k] = 0.f;
    }

    const float4* gp4 = (const float4*)(g_proj + (size_t)bh * N_ * O_);
    float4* Pbuf4 = (float4*)s_P[grp];
    const uint32_t onef = 0x3F800000u;

    for (int tt = 0; tt < 4; tt++) {
        int j0 = grp * 256 + tt * 64;
        if (tt) asm volatile("bar.sync %0, %1;" :: "r"(barid), "r"(128) : "memory");
#pragma unroll
        for (int u = 0; u < 4; u++) {
            int idx = lt + u * 128;
            Pbuf4[(idx >> 3) * PS4 + (idx & 7)] = gp4[j0 * 8 + idx];
        }
        asm volatile("bar.sync %0, %1;" :: "r"(barid), "r"(128) : "memory");

#pragma unroll
        for (int w4 = 0; w4 < 2; w4++) {
            uint2 wv = ap[(j0 >> 5) + w4];
            unsigned wlw = wv.x >> q4;
            unsigned whw = wv.y >> q4;
#pragma unroll
            for (int sub = 0; sub < 4; sub++) {
                int jb = (w4 * 4 + sub) * 8;
                ulonglong2 sq0 = s_ssd[j0 + jb + q4];        // j slot
                ulonglong2 sq1 = s_ssd[j0 + jb + q4 + 4];    // j+4 slot

                // packed logits for (row_lo,row_hi) pair
                unsigned long long v0 = add2(dd, sq0.x);
                unsigned long long v1 = add2(dd, sq1.x);
                unsigned long long a01 = fma2p(C04, v0 & ABS2, fma2p(C06, v0, sq0.y));
                unsigned long long a23 = fma2p(C04, v1 & ABS2, fma2p(C06, v1, sq1.y));
                float a0, a1, a2, a3;
                upk2(a01, a0, a1);
                upk2(a23, a2, a3);

                float e0 = ((wlw >> (sub * 8)) & 1u)     ? ex2f(a0) : 0.f;
                float e1 = ((whw >> (sub * 8)) & 1u)     ? ex2f(a1) : 0.f;
                float e2 = ((wlw >> (sub * 8 + 4)) & 1u) ? ex2f(a2) : 0.f;
                float e3 = ((whw >> (sub * 8 + 4)) & 1u) ? ex2f(a3) : 0.f;
                uint32_t u0 = __float_as_uint(e0), u1 = __float_as_uint(e1);
                uint32_t u2 = __float_as_uint(e2), u3 = __float_as_uint(e3);

                float4 blo = Pbuf4[(jb + q4) * PS4 + g];
                float4 bhi = Pbuf4[(jb + q4 + 4) * PS4 + g];

#pragma unroll
                for (int nc = 0; nc < 4; nc++) {
                    uint32_t b0 = __float_as_uint(((const float*)&blo)[nc]);
                    uint32_t b1 = __float_as_uint(((const float*)&bhi)[nc]);
                    mma8(acc[nc], u0, u1, u2, u3, b0, b1);
                }
                mma8(accd, u0, u1, u2, u3, onef, onef);
            }
        }
    }

    float dn_lo = accd[0], dn_hi = accd[2];

    __syncthreads();
    float* red = &s_P[0][0];
    float* dnp = (float*)s_ssd;
    if (grp > 0) {
        int lb = wl4 * 32 + lane;
        float* ra = red + ((grp - 1) * 128 + lb) * 17;
#pragma unroll
        for (int nc = 0; nc < 4; nc++)
#pragma unroll
            for (int k = 0; k < 4; k++) ra[nc * 4 + k] = acc[nc][k];
        dnp[(grp - 1) * 256 + lb * 2]     = dn_lo;
        dnp[(grp - 1) * 256 + lb * 2 + 1] = dn_hi;
    }
    __syncthreads();
    if (grp == 0) {
        int lb = wl4 * 32 + lane;
#pragma unroll
        for (int pg = 0; pg < 3; pg++) {
            const float* ra = red + (pg * 128 + lb) * 17;
#pragma unroll
            for (int nc = 0; nc < 4; nc++)
#pragma unroll
                for (int k = 0; k < 4; k++) acc[nc][k] += ra[nc * 4 + k];
            dn_lo += dnp[pg * 256 + lb * 2];
            dn_hi += dnp[pg * 256 + lb * 2 + 1];
        }
        float inv_lo = dn_lo > 0.f ? 1.f / dn_lo : 0.f;
        float inv_hi = dn_hi > 0.f ? 1.f / dn_hi : 0.f;

        float* orow_lo = out + ((size_t)b * N_ + row0 + r_lo) * (H_ * O_) + h * O_;
        float* orow_hi = out + ((size_t)b * N_ + row0 + r_hi) * (H_ * O_) + h * O_;
#pragma unroll
        for (int nc = 0; nc < 4; nc++) {
            float2 vlo = make_float2(acc[nc][0] * inv_lo, acc[nc][1] * inv_lo);
            float2 vhi = make_float2(acc[nc][2] * inv_hi, acc[nc][3] * inv_hi);
            *(float2*)(orow_lo + nc * 8 + 2 * q4) = vlo;
            *(float2*)(orow_hi + nc * 8 + 2 * q4) = vhi;
        }
    }
}

// =============== launch ===============
extern "C" void kernel_launch(void* const* d_in, const int* in_sizes, int n_in,
                              void* d_out, int out_size) {
    const float* x        = (const float*)d_in[0];
    const int*   adj      = (const int*)  d_in[1];
    const float* prior    = (const float*)d_in[2];
    const float* beta     = (const float*)d_in[3];
    const float* weight   = (const float*)d_in[4];
    const float* attn_src = (const float*)d_in[5];
    const float* attn_dst = (const float*)d_in[6];
    const float* bias     = (const float*)d_in[7];
    float* out = (float*)d_out;

    k01_prep<<<384, 256>>>(adj, x, weight, bias, attn_src, attn_dst, beta, prior);
    k2_attn<<<dim3(N_/64, H_, B_), 512>>>(out);
}

// round 16
// speedup vs baseline: 1.0366x; 1.0366x over previous
#include <cuda_runtime.h>
#include <cstdint>

#define B_ 8
#define N_ 1024
#define I_ 64
#define O_ 32
#define NW 32
#define H_ 4
#define PS4 10             // P-tile row stride in float4 (phase-conflict-free)
#define XS 68              // x smem stride (floats)
#define WS 136             // W smem stride (floats)
#define GRID_ 296
#define LOG2E 1.4426950408889634f

// ---- device scratch ----
__device__ float    g_proj[B_*H_*N_*O_];    // [bh][j][operm], tf32-rounded
__device__ float2   g_srcsp[B_*H_*N_];      // (src*L, gain*prior*L)
__device__ float    g_dstsc[B_*H_*N_];      // dst*L
__device__ unsigned g_adjp[(N_/2)*NW*2];    // row-pair interleaved adjacency bits
__device__ unsigned g_barrier;              // monotonic epoch counter (never reset)

__device__ __forceinline__ float tf32r(float x) {
    uint32_t r;
    asm("cvt.rna.tf32.f32 %0, %1;" : "=r"(r) : "f"(x));
    return __uint_as_float(r);
}
__device__ __forceinline__ uint32_t tf32u(float x) {
    uint32_t r;
    asm("cvt.rna.tf32.f32 %0, %1;" : "=r"(r) : "f"(x));
    return r;
}
__device__ __forceinline__ float ex2f(float x) {
    float r;
    asm("ex2.approx.f32 %0, %1;" : "=f"(r) : "f"(x));
    return r;
}
__device__ __forceinline__ void mma8(float* c, uint32_t a0, uint32_t a1, uint32_t a2,
                                     uint32_t a3, uint32_t b0, uint32_t b1) {
    asm volatile(
        "mma.sync.aligned.m16n8k8.row.col.f32.tf32.tf32.f32 "
        "{%0,%1,%2,%3}, {%4,%5,%6,%7}, {%8,%9}, {%0,%1,%2,%3};"
        : "+f"(c[0]), "+f"(c[1]), "+f"(c[2]), "+f"(c[3])
        : "r"(a0), "r"(a1), "r"(a2), "r"(a3), "r"(b0), "r"(b1));
}

// wrap-safe monotonic grid barrier (graph-capturable, no reset needed)
__device__ __forceinline__ void grid_barrier() {
    __syncthreads();
    if (threadIdx.x == 0) {
        __threadfence();
        unsigned v = atomicAdd(&g_barrier, 1u);
        unsigned target = v - (v % GRID_) + GRID_;
        unsigned cur;
        do {
            asm volatile("ld.acquire.gpu.u32 %0, [%1];" : "=r"(cur) : "l"(&g_barrier));
        } while ((int)(cur - target) < 0);
        __threadfence();
    }
    __syncthreads();
}

// =============== fused kernel: phase A (pack + proj/scores) | barrier | phase C (attn) ===============
__global__ __launch_bounds__(512, 2) void k_fused(
    const int* __restrict__ adj,
    const float* __restrict__ x, const float* __restrict__ weight,
    const float* __restrict__ bias, const float* __restrict__ attn_src,
    const float* __restrict__ attn_dst, const float* __restrict__ beta,
    const float* __restrict__ prior, float* __restrict__ out)
{
    __shared__ union {
        struct {                            // phase A  (~45.7KB)
            float x[32*XS];
            float w[I_*WS];
            float ws[H_*I_];
            float wd[H_*I_];
            float c[8];
        } a;
        struct {                            // phase C  (49KB)
            float4 ss2[N_/2];
            float  P[4][64*PS4*4];
        } b;
    } su;

    int tid = threadIdx.x, lane = tid & 31, w = tid >> 5;
    int bid = blockIdx.x;
    int g = lane >> 2, q4 = lane & 3;

    // ================= PHASE A =================
    // pack: warps 8-15 of blocks 0..127, one adjacency row per warp
    if (bid < 128 && w >= 8) {
        int i = bid * 8 + (w - 8);
        const int4* a4 = (const int4*)(adj + (size_t)i * N_);
        int4 v[8];
#pragma unroll
        for (int c4 = 0; c4 < 8; c4++) v[c4] = a4[c4 * 32 + lane];
        int gs = lane >> 3;
        unsigned gmask = 0xFFu << (gs * 8);
        int sh = (lane & 7) * 4;
        int pidx = (i >> 4) * 8 + (i & 7);
        int comp = (i >> 3) & 1;
#pragma unroll
        for (int c4 = 0; c4 < 8; c4++) {
            unsigned nib = (unsigned)(v[c4].x != 0) | ((unsigned)(v[c4].y != 0) << 1)
                         | ((unsigned)(v[c4].z != 0) << 2) | ((unsigned)(v[c4].w != 0) << 3);
            unsigned word = __reduce_or_sync(gmask, nib << sh);
            if ((lane & 7) == 0) g_adjp[(pidx * NW + c4 * 4 + gs) * 2 + comp] = word;
        }
    }

    bool projb = (bid < 256) && (tid < 256);
    int g0 = bid * 32;                      // proj node base (valid when projb)
    int b = g0 >> 10;

    if (projb) {
        // stage x [32 x 64], padded
        const float4* gx4 = (const float4*)(x + (size_t)g0 * I_);
#pragma unroll
        for (int u = 0; u < 2; u++) {
            int idx = tid + u * 256;
            int node = idx >> 4, i4 = idx & 15;
            *(float4*)(su.a.x + node * XS + i4 * 4) = gx4[idx];
        }
        // stage W as [i][ho], padded
        const float4* gw4 = (const float4*)weight;
#pragma unroll
        for (int u = 0; u < 8; u++) {
            int l4 = tid + u * 256;
            int h = l4 >> 9, i = (l4 >> 3) & 63, o4 = l4 & 7;
            *(float4*)(su.a.w + i * WS + h * O_ + o4 * 4) = gw4[l4];
        }
        // score contraction vectors
        {
            int h = tid >> 6;
            const float4* wrow = (const float4*)(weight + (size_t)tid * O_);
            const float4* as4  = (const float4*)(attn_src + h * O_);
            const float4* ad4  = (const float4*)(attn_dst + h * O_);
            float accs = 0.f, accd = 0.f;
#pragma unroll
            for (int o4 = 0; o4 < 8; o4++) {
                float4 wv = wrow[o4], av = as4[o4], dv = ad4[o4];
                accs += wv.x*av.x + wv.y*av.y + wv.z*av.z + wv.w*av.w;
                accd += wv.x*dv.x + wv.y*dv.y + wv.z*dv.z + wv.w*dv.w;
            }
            su.a.ws[tid] = accs * LOG2E;
            su.a.wd[tid] = accd * LOG2E;
        }
        if (tid < 8) {
            int hh = tid & 3;
            const float* bb = bias + hh * O_;
            const float* aa = (tid < 4 ? attn_src : attn_dst) + hh * O_;
            float c = 0.f;
#pragma unroll
            for (int o = 0; o < O_; o++) c += bb[o] * aa[o];
            su.a.c[tid] = c * LOG2E;
        }
    }
    __syncthreads();

    float pacc[4][4];
    if (projb) {                            // tf32 MMA projection
        int wn = w >> 1, mt = w & 1;
#pragma unroll
        for (int nt = 0; nt < 4; nt++) {
            float b0 = bias[wn * 32 + nt * 8 + 2 * q4];
            float b1 = bias[wn * 32 + nt * 8 + 2 * q4 + 1];
            pacc[nt][0] = b0; pacc[nt][1] = b1; pacc[nt][2] = b0; pacc[nt][3] = b1;
        }
#pragma unroll
        for (int ks = 0; ks < 8; ks++) {
            int i0 = ks * 8;
            uint32_t a0 = tf32u(su.a.x[(mt*16 + g    ) * XS + i0 + q4]);
            uint32_t a1 = tf32u(su.a.x[(mt*16 + g + 8) * XS + i0 + q4]);
            uint32_t a2 = tf32u(su.a.x[(mt*16 + g    ) * XS + i0 + q4 + 4]);
            uint32_t a3 = tf32u(su.a.x[(mt*16 + g + 8) * XS + i0 + q4 + 4]);
#pragma unroll
            for (int nt = 0; nt < 4; nt++) {
                int col = wn * 32 + nt * 8 + g;
                uint32_t b0 = tf32u(su.a.w[(i0 + q4    ) * WS + col]);
                uint32_t b1 = tf32u(su.a.w[(i0 + q4 + 4) * WS + col]);
                mma8(pacc[nt], a0, a1, a2, a3, b0, b1);
            }
        }
    }
    __syncthreads();                        // all s_w reads done

    if (projb) {                            // stage epilogue to smem (reuse a.w)
        int wn = w >> 1, mt = w & 1;
        float* s_out = su.a.w;              // [node][128: h*32+operm]
#pragma unroll
        for (int nt = 0; nt < 4; nt++) {
#pragma unroll
            for (int c2 = 0; c2 < 2; c2++) {
                int ho = wn * 32 + nt * 8 + 2 * q4 + c2;
                int h = ho >> 5, o = ho & 31;
                int col = h * 32 + (o & 7) * 4 + (o >> 3);
                s_out[(mt*16 + g    ) * 128 + col] = tf32r(pacc[nt][c2]);
                s_out[(mt*16 + g + 8) * 128 + col] = tf32r(pacc[nt][c2 + 2]);
            }
        }
    }
    __syncthreads();

    if (projb) {
        // coalesced proj store
        int n0 = g0 & 1023;
        const float4* so4 = (const float4*)su.a.w;
#pragma unroll
        for (int u = 0; u < 4; u++) {
            int idx = tid + u * 256;        // 1024 float4
            int n = idx >> 5, c4 = idx & 31;
            int h = c4 >> 3, o4 = c4 & 7;
            ((float4*)g_proj)[((size_t)(b * H_ + h) * N_ + n0 + n) * 8 + o4] = so4[idx];
        }
        // scores (exact fp32)
        int role = tid >> 7, local = tid & 127;
        int n = local >> 2, hs = local & 3;
        const float4* xv4 = (const float4*)(su.a.x + n * XS);
        const float4* wv4 = (const float4*)((role ? su.a.wd : su.a.ws) + hs * I_);
        float sc = su.a.c[role * 4 + hs];
#pragma unroll
        for (int i4 = 0; i4 < I_/4; i4++) {
            float4 xv = xv4[i4], wv = wv4[i4];
            sc += xv.x*wv.x + xv.y*wv.y + xv.z*wv.z + xv.w*wv.w;
        }
        int gidx = g0 + n;
        int idx = (b * H_ + hs) * N_ + (gidx & 1023);
        if (role) {
            g_dstsc[idx] = sc;
        } else {
            float bt = beta[hs];
            float gain = ((bt > 20.f) ? bt : log1pf(__expf(bt))) * LOG2E;
            g_srcsp[idx] = make_float2(sc, gain * prior[gidx]);
        }
    }

    // ================= BARRIER =================
    grid_barrier();

    // ================= PHASE C: attention =================
    int grp = w >> 2;
    int wl4 = w & 3;
    int lt  = tid & 127;
    int barid = grp + 1;
    const uint32_t onef = 0x3F800000u;

    for (int ti = 0; ti < 2; ti++) {
        int tix = bid + ti * GRID_;
        if (tix >= 512) break;
        __syncthreads();                    // smem reuse guard

        int rt = tix & 15, h = (tix >> 4) & 3, bb2 = tix >> 6;
        int bh = bb2 * H_ + h;
        int row0 = rt * 64;

        // stage paired ss
        const float2* gss = g_srcsp + (size_t)bh * N_;
#pragma unroll
        for (int u = 0; u < 2; u++) {
            int j = tid + u * 512;
            float2 ss = gss[j];
            ((float2*)&su.b.ss2[(j >> 3) * 4 + (j & 3)])[(j >> 2) & 1] = ss;
        }
        __syncthreads();

        int r_lo = wl4 * 16 + g, r_hi = r_lo + 8;
        float dst_lo = g_dstsc[(size_t)bh * N_ + row0 + r_lo];
        float dst_hi = g_dstsc[(size_t)bh * N_ + row0 + r_hi];
        int pidx = ((row0 + wl4 * 16) >> 4) * 8 + g;
        const uint2* ap = (const uint2*)g_adjp + (size_t)pidx * NW;

        float acc[4][4], accd[4];
#pragma unroll
        for (int nc = 0; nc < 4; nc++) {
            accd[nc] = 0.f;
#pragma unroll
            for (int k = 0; k < 4; k++) acc[nc][k] = 0.f;
        }

        const float4* gp4 = (const float4*)(g_proj + (size_t)bh * N_ * O_);
        float4* Pbuf4 = (float4*)su.b.P[grp];

        for (int tt = 0; tt < 4; tt++) {
            int j0 = grp * 256 + tt * 64;
            if (tt) asm volatile("bar.sync %0, %1;" :: "r"(barid), "r"(128) : "memory");
#pragma unroll
            for (int u = 0; u < 4; u++) {
                int idx = lt + u * 128;
                Pbuf4[(idx >> 3) * PS4 + (idx & 7)] = gp4[j0 * 8 + idx];
            }
            asm volatile("bar.sync %0, %1;" :: "r"(barid), "r"(128) : "memory");

#pragma unroll
            for (int w4 = 0; w4 < 2; w4++) {
                uint2 wv = ap[(j0 >> 5) + w4];
                unsigned wlw = wv.x >> q4;
                unsigned whw = wv.y >> q4;
#pragma unroll
                for (int sub = 0; sub < 4; sub++) {
                    int jb = (w4 * 4 + sub) * 8;
                    float4 sq = su.b.ss2[((j0 + jb) >> 3) * 4 + q4];

                    float v0l = dst_lo + sq.x, v0h = dst_hi + sq.x;
                    float v1l = dst_lo + sq.z, v1h = dst_hi + sq.z;
                    float a0 = fmaf(0.4f, fabsf(v0l), fmaf(0.6f, v0l, sq.y));
                    float a1 = fmaf(0.4f, fabsf(v0h), fmaf(0.6f, v0h, sq.y));
                    float a2 = fmaf(0.4f, fabsf(v1l), fmaf(0.6f, v1l, sq.w));
                    float a3 = fmaf(0.4f, fabsf(v1h), fmaf(0.6f, v1h, sq.w));

                    float e0 = ((wlw >> (sub * 8)) & 1u)     ? ex2f(a0) : 0.f;
                    float e1 = ((whw >> (sub * 8)) & 1u)     ? ex2f(a1) : 0.f;
                    float e2 = ((wlw >> (sub * 8 + 4)) & 1u) ? ex2f(a2) : 0.f;
                    float e3 = ((whw >> (sub * 8 + 4)) & 1u) ? ex2f(a3) : 0.f;
                    uint32_t u0 = __float_as_uint(e0), u1 = __float_as_uint(e1);
                    uint32_t u2 = __float_as_uint(e2), u3 = __float_as_uint(e3);

                    float4 blo = Pbuf4[(jb + q4) * PS4 + g];
                    float4 bhi = Pbuf4[(jb + q4 + 4) * PS4 + g];

#pragma unroll
                    for (int nc = 0; nc < 4; nc++) {
                        uint32_t b0 = __float_as_uint(((const float*)&blo)[nc]);
                        uint32_t b1 = __float_as_uint(((const float*)&bhi)[nc]);
                        mma8(acc[nc], u0, u1, u2, u3, b0, b1);
                    }
                    mma8(accd, u0, u1, u2, u3, onef, onef);
                }
            }
        }

        float dn_lo = accd[0], dn_hi = accd[2];

        // merge 4 j-quarters
        __syncthreads();
        float* red = &su.b.P[0][0];
        float* dnp = (float*)su.b.ss2;
        if (grp > 0) {
            int lb = wl4 * 32 + lane;
            float* ra = red + ((grp - 1) * 128 + lb) * 17;
#pragma unroll
            for (int nc = 0; nc < 4; nc++)
#pragma unroll
                for (int k = 0; k < 4; k++) ra[nc * 4 + k] = acc[nc][k];
            dnp[(grp - 1) * 256 + lb * 2]     = dn_lo;
            dnp[(grp - 1) * 256 + lb * 2 + 1] = dn_hi;
        }
        __syncthreads();
        if (grp == 0) {
            int lb = wl4 * 32 + lane;
#pragma unroll
            for (int pg = 0; pg < 3; pg++) {
                const float* ra = red + (pg * 128 + lb) * 17;
#pragma unroll
                for (int nc = 0; nc < 4; nc++)
#pragma unroll
                    for (int k = 0; k < 4; k++) acc[nc][k] += ra[nc * 4 + k];
                dn_lo += dnp[pg * 256 + lb * 2];
                dn_hi += dnp[pg * 256 + lb * 2 + 1];
            }
            float inv_lo = dn_lo > 0.f ? 1.f / dn_lo : 0.f;
            float inv_hi = dn_hi > 0.f ? 1.f / dn_hi : 0.f;

            float* orow_lo = out + ((size_t)bb2 * N_ + row0 + r_lo) * (H_ * O_) + h * O_;
            float* orow_hi = out + ((size_t)bb2 * N_ + row0 + r_hi) * (H_ * O_) + h * O_;
#pragma unroll
            for (int nc = 0; nc < 4; nc++) {
                float2 vlo = make_float2(acc[nc][0] * inv_lo, acc[nc][1] * inv_lo);
                float2 vhi = make_float2(acc[nc][2] * inv_hi, acc[nc][3] * inv_hi);
                *(float2*)(orow_lo + nc * 8 + 2 * q4) = vlo;
                *(float2*)(orow_hi + nc * 8 + 2 * q4) = vhi;
            }
        }
    }
}

// =============== launch ===============
extern "C" void kernel_launch(void* const* d_in, const int* in_sizes, int n_in,
                              void* d_out, int out_size) {
    const float* x        = (const float*)d_in[0];
    const int*   adj      = (const int*)  d_in[1];
    const float* prior    = (const float*)d_in[2];
    const float* beta     = (const float*)d_in[3];
    const float* weight   = (const float*)d_in[4];
    const float* attn_src = (const float*)d_in[5];
    const float* attn_dst = (const float*)d_in[6];
    const float* bias     = (const float*)d_in[7];
    float* out = (float*)d_out;

    k_fused<<<GRID_, 512>>>(adj, x, weight, bias, attn_src, attn_dst, beta, prior, out);
}